// round 5
// baseline (speedup 1.0000x reference)
#include <cuda_runtime.h>
#include <math.h>

#define TT 1024
#define BB 32
#define DD 1024
#define BD (BB*DD)          /* 32768    */
#define TBD (TT*BB*DD)      /* 33554432 */

/* ---------- packed f32x2 helpers (sm_103a FFMA2) ---------- */
__device__ __forceinline__ void fma2(unsigned long long& acc,
                                     unsigned long long a,
                                     unsigned long long b) {
    asm("fma.rn.f32x2 %0, %1, %2, %0;" : "+l"(acc) : "l"(a), "l"(b));
}
__device__ __forceinline__ unsigned long long pack2(float lo, float hi) {
    unsigned long long r;
    asm("mov.b64 %0, {%1, %2};" : "=l"(r)
        : "r"(__float_as_uint(lo)), "r"(__float_as_uint(hi)));
    return r;
}
__device__ __forceinline__ float pairsum(unsigned long long v) {
    float lo = __uint_as_float((unsigned int)(v & 0xffffffffull));
    float hi = __uint_as_float((unsigned int)(v >> 32));
    return lo + hi;
}

/* ---------- scratch: transposed recurrent weights, L2-resident ----------
 * g_wT[mat][k4][d] = float4{ W[d][4*k4 .. 4*k4+3] },  mat 0 = R_h, 1 = R_delta
 * 2 * 256 * 1024 * 16B = 8 MB static __device__ array (no allocation).    */
__device__ float4 g_wT[2][256][1024];

__global__ __launch_bounds__(256) void transpose_w_kernel(
    const float* __restrict__ Rh, const float* __restrict__ Rd)
{
    int idx = blockIdx.x * blockDim.x + threadIdx.x;   /* 2*256*1024 total */
    int d   = idx & (DD - 1);
    int k4  = (idx >> 10) & 255;
    int mat = idx >> 18;
    const float* W = mat ? Rd : Rh;
    float4 v = *(const float4*)(W + (size_t)d * DD + k4 * 4);
    g_wT[mat][k4][d] = v;
}

/* ================= precompute GEMM (FFMA2) =================
 * C[m,n] = sum_k x[m,k]*W[n,k] + bias[n], m<32768, n<2048
 *   n <  1024 : W=R_x,     bias=b,       dst = out section    (stash xRx[t])
 *   n >= 1024 : W=W_delta, bias=b_delta, dst = h section +BD  (stash xWd[t])
 */
#define BM 64
#define BN 64
#define BKK 16
#define PAD 72   /* row stride: 72 floats = 288 B, 16B-aligned sublocs */

__global__ __launch_bounds__(256) void pre_gemm_kernel(
    const float* __restrict__ x,
    const float* __restrict__ Rx,
    const float* __restrict__ Wdl,
    const float* __restrict__ bias_v,
    const float* __restrict__ bias_d,
    float* __restrict__ outsec,
    float* __restrict__ hsec)
{
    __shared__ float As[BKK][PAD];
    __shared__ float Ws[BKK][PAD];

    const int m0  = blockIdx.x * BM;
    const int n0g = blockIdx.y * BN;
    const int sel = (n0g >= DD) ? 1 : 0;
    const float* __restrict__ W    = sel ? Wdl    : Rx;
    const float* __restrict__ bias = sel ? bias_d : bias_v;
    float* __restrict__ dst = sel ? (hsec + BD) : outsec;
    const int n0 = n0g & (DD - 1);

    const int tid  = threadIdx.x;
    const int lrow = tid >> 2;
    const int lk4  = (tid & 3) * 4;
    const int tx   = tid & 15;          /* n dir */
    const int ty   = tid >> 4;          /* m dir */

    /* acc2[p][j]: packed pair of rows (ty*4+2p, ty*4+2p+1), col tx*4+j */
    unsigned long long acc2[2][4];
    #pragma unroll
    for (int p = 0; p < 2; p++)
        #pragma unroll
        for (int j = 0; j < 4; j++) acc2[p][j] = 0ull;

    const float* xa = x + (size_t)(m0 + lrow) * DD;
    const float* wa = W + (size_t)(n0 + lrow) * DD;

    for (int kk = 0; kk < DD; kk += BKK) {
        float4 a4 = *(const float4*)(xa + kk + lk4);
        float4 w4 = *(const float4*)(wa + kk + lk4);
        As[lk4 + 0][lrow] = a4.x; As[lk4 + 1][lrow] = a4.y;
        As[lk4 + 2][lrow] = a4.z; As[lk4 + 3][lrow] = a4.w;
        Ws[lk4 + 0][lrow] = w4.x; Ws[lk4 + 1][lrow] = w4.y;
        Ws[lk4 + 2][lrow] = w4.z; Ws[lk4 + 3][lrow] = w4.w;
        __syncthreads();

        #pragma unroll
        for (int k = 0; k < BKK; k++) {
            ulonglong2 a2 = *(const ulonglong2*)&As[k][ty * 4];  /* i-pairs, free */
            float4 wf = *(const float4*)&Ws[k][tx * 4];
            unsigned long long w0 = pack2(wf.x, wf.x);
            unsigned long long w1 = pack2(wf.y, wf.y);
            unsigned long long w2 = pack2(wf.z, wf.z);
            unsigned long long w3 = pack2(wf.w, wf.w);
            fma2(acc2[0][0], a2.x, w0); fma2(acc2[0][1], a2.x, w1);
            fma2(acc2[0][2], a2.x, w2); fma2(acc2[0][3], a2.x, w3);
            fma2(acc2[1][0], a2.y, w0); fma2(acc2[1][1], a2.y, w1);
            fma2(acc2[1][2], a2.y, w2); fma2(acc2[1][3], a2.y, w3);
        }
        __syncthreads();
    }

    #pragma unroll
    for (int p = 0; p < 2; p++) {
        #pragma unroll
        for (int j = 0; j < 4; j++) {
            const int col = n0 + tx * 4 + j;
            const float bb = bias[col];
            float lo = __uint_as_float((unsigned int)(acc2[p][j] & 0xffffffffull));
            float hi = __uint_as_float((unsigned int)(acc2[p][j] >> 32));
            dst[(size_t)(m0 + ty * 4 + 2 * p + 0) * DD + col] = lo + bb;
            dst[(size_t)(m0 + ty * 4 + 2 * p + 1) * DD + col] = hi + bb;
        }
    }
}

/* ================= persistent recurrence =================
 * 128 CTAs x 256 threads, all co-resident (grid <= 148 SMs) -> spin barrier
 * safe. CTA = (dg, bg): d in [32*dg, 32*dg+32), b in [8*bg, 8*bg+8).
 * Warp w = k-eighth [128*w, 128*w+128), lane = d-local.
 *   - weight loads: coalesced 512B LDG from transposed L2-resident g_wT
 *   - h loads: uniform-address broadcast LDG (1 sector each)
 *   - packed FFMA2: 32 per warp per k4
 * Partial sums combined across the 8 k-eighth warps via smem staging,
 * then a fully coalesced elementwise epilogue writes out[t] and h[t+1].
 */
__device__ unsigned int g_bar = 0;
__device__ unsigned int g_gen = 0;

__device__ __forceinline__ void grid_sync() {
    __syncthreads();
    if (threadIdx.x == 0) {
        __threadfence();
        unsigned int gen = *((volatile unsigned int*)&g_gen);
        if (atomicAdd(&g_bar, 1) == 127u) {           /* last arriver */
            atomicExch(&g_bar, 0);
            __threadfence();
            atomicAdd(&g_gen, 1);
        } else {
            while (*((volatile unsigned int*)&g_gen) == gen) __nanosleep(64);
        }
        __threadfence();
    }
    __syncthreads();
}

__global__ __launch_bounds__(256, 1) void rec_kernel(
    const float* __restrict__ x,
    const float* __restrict__ bgate,
    float* __restrict__ outsec,
    float* __restrict__ hsec)
{
    __shared__ float sRed[8][2][8][32];   /* [kwarp][mat][b][d-lane] 16 KB */

    const int dg   = blockIdx.x >> 2;       /* 0..31 */
    const int bgrp = blockIdx.x & 3;        /* 0..3  */
    const int d0   = dg * 32;
    const int b0   = bgrp * 8;
    const int w    = threadIdx.x >> 5;      /* k-eighth 0..7 */
    const int lane = threadIdx.x & 31;      /* d-local       */
    const int k4b  = w * 32;                /* k4 in [k4b, k4b+32) */

    const int eb   = threadIdx.x >> 5;      /* epilogue: b-local 0..7  */
    const int ed   = threadIdx.x & 31;      /* epilogue: d-local 0..31 */
    const float bgv = bgate[d0 + ed];

    for (int t = 0; t < TT; t++) {
        unsigned long long accv[8], accd[8];
        #pragma unroll
        for (int b = 0; b < 8; b++) { accv[b] = 0ull; accd[b] = 0ull; }

        const float* hbase = hsec + (size_t)t * BD;

        #pragma unroll 2
        for (int k4 = k4b; k4 < k4b + 32; k4++) {
            ulonglong2 wv = *(const ulonglong2*)&g_wT[0][k4][d0 + lane];
            ulonglong2 wd = *(const ulonglong2*)&g_wT[1][k4][d0 + lane];
            #pragma unroll
            for (int b = 0; b < 8; b++) {
                ulonglong2 h2 = __ldg((const ulonglong2*)
                                      (hbase + (size_t)(b0 + b) * DD + k4 * 4));
                fma2(accv[b], wv.x, h2.x);
                fma2(accv[b], wv.y, h2.y);
                fma2(accd[b], wd.x, h2.x);
                fma2(accd[b], wd.y, h2.y);
            }
        }

        #pragma unroll
        for (int b = 0; b < 8; b++) {
            sRed[w][0][b][lane] = pairsum(accv[b]);
            sRed[w][1][b][lane] = pairsum(accd[b]);
        }
        __syncthreads();

        /* ---- elementwise epilogue: thread -> (b0+eb, d0+ed), coalesced ---- */
        {
            float sumv = 0.f, sumd = 0.f;
            #pragma unroll
            for (int kw = 0; kw < 8; kw++) {
                sumv += sRed[kw][0][eb][ed];
                sumd += sRed[kw][1][eb][ed];
            }
            const size_t idx = (size_t)t * BD + (size_t)(b0 + eb) * DD + (d0 + ed);

            const float v     = outsec[idx]    + sumv;   /* stash xRx + h@Rh^T */
            const float dpre  = hsec[idx + BD] + sumd;   /* stash xWd + h@Rd^T */
            const float delta = 1.f / (1.f + expf(-dpre));
            const float hp    = hsec[idx];
            const float hn    = (1.f - delta) * hp + delta * tanhf(v);
            const float z     = hn + x[idx] + bgv;
            const float sig   = 1.f / (1.f + expf(-z));

            outsec[idx]    = hn * z * sig;               /* out[t]  */
            hsec[idx + BD] = hn;                         /* h[t+1]  */
        }

        grid_sync();   /* publish h[t+1] to all CTAs; also guards sRed reuse */
    }
}

extern "C" void kernel_launch(void* const* d_in, const int* in_sizes, int n_in,
                              void* d_out, int out_size)
{
    const float* x   = (const float*)d_in[0];
    const float* h0  = (const float*)d_in[1];
    const float* Rh  = (const float*)d_in[2];
    const float* Rx  = (const float*)d_in[3];
    const float* Rd  = (const float*)d_in[4];
    const float* Wdl = (const float*)d_in[5];
    const float* b   = (const float*)d_in[6];
    const float* bd  = (const float*)d_in[7];
    const float* bgt = (const float*)d_in[8];

    float* outsec = (float*)d_out;          /* [T,B,D] outputs        */
    float* hsec   = outsec + (size_t)TBD;   /* [T+1,B,D] hidden states */

    /* h[0] = h0 */
    cudaMemcpyAsync(hsec, h0, (size_t)BD * sizeof(float),
                    cudaMemcpyDeviceToDevice, 0);

    /* transposed recurrent weights into L2-resident scratch */
    transpose_w_kernel<<<2 * 256 * 1024 / 256, 256>>>(Rh, Rd);

    /* big input GEMM: stash xRx into out[t], xWd into h[t+1] */
    dim3 pgrid(TT * BB / BM, 2 * DD / BN);  /* (512, 32) */
    pre_gemm_kernel<<<pgrid, 256>>>(x, Rx, Wdl, b, bd, outsec, hsec);

    /* single persistent kernel for the whole scan */
    rec_kernel<<<128, 256>>>(x, bgt, outsec, hsec);
}

// round 6
// speedup vs baseline: 1.1731x; 1.1731x over previous
#include <cuda_runtime.h>
#include <math.h>

#define TT 1024
#define BB 32
#define DD 1024
#define BD (BB*DD)          /* 32768    */
#define TBD (TT*BB*DD)      /* 33554432 */

/* ---------- packed f32x2 helpers (sm_103a FFMA2) ---------- */
__device__ __forceinline__ void fma2(unsigned long long& acc,
                                     unsigned long long a,
                                     unsigned long long b) {
    asm("fma.rn.f32x2 %0, %1, %2, %0;" : "+l"(acc) : "l"(a), "l"(b));
}
__device__ __forceinline__ unsigned long long pack2(float lo, float hi) {
    unsigned long long r;
    asm("mov.b64 %0, {%1, %2};" : "=l"(r)
        : "r"(__float_as_uint(lo)), "r"(__float_as_uint(hi)));
    return r;
}
__device__ __forceinline__ float lo32(unsigned long long v) {
    return __uint_as_float((unsigned int)(v & 0xffffffffull));
}
__device__ __forceinline__ float hi32(unsigned long long v) {
    return __uint_as_float((unsigned int)(v >> 32));
}

/* transposed hidden state, double-buffered: g_hT[par][k][b], 256 KB static */
__device__ float g_hT[2][DD][BB];

/* ================= precompute GEMM (FFMA2) =================
 * C[m,n] = sum_k x[m,k]*W[n,k] + bias[n], m<32768, n<2048
 *   n <  1024 : W=R_x,     bias=b,       dst = out section    (stash xRx[t])
 *   n >= 1024 : W=W_delta, bias=b_delta, dst = h section +BD  (stash xWd[t])
 */
#define BM 64
#define BN 64
#define BKK 16
#define PAD 72

__global__ __launch_bounds__(256) void pre_gemm_kernel(
    const float* __restrict__ x,
    const float* __restrict__ Rx,
    const float* __restrict__ Wdl,
    const float* __restrict__ bias_v,
    const float* __restrict__ bias_d,
    float* __restrict__ outsec,
    float* __restrict__ hsec)
{
    __shared__ float As[BKK][PAD];
    __shared__ float Ws[BKK][PAD];

    const int m0  = blockIdx.x * BM;
    const int n0g = blockIdx.y * BN;
    const int sel = (n0g >= DD) ? 1 : 0;
    const float* __restrict__ W    = sel ? Wdl    : Rx;
    const float* __restrict__ bias = sel ? bias_d : bias_v;
    float* __restrict__ dst = sel ? (hsec + BD) : outsec;
    const int n0 = n0g & (DD - 1);

    const int tid  = threadIdx.x;
    const int lrow = tid >> 2;
    const int lk4  = (tid & 3) * 4;
    const int tx   = tid & 15;          /* n dir */
    const int ty   = tid >> 4;          /* m dir */

    unsigned long long acc2[2][4];
    #pragma unroll
    for (int p = 0; p < 2; p++)
        #pragma unroll
        for (int j = 0; j < 4; j++) acc2[p][j] = 0ull;

    const float* xa = x + (size_t)(m0 + lrow) * DD;
    const float* wa = W + (size_t)(n0 + lrow) * DD;

    for (int kk = 0; kk < DD; kk += BKK) {
        float4 a4 = *(const float4*)(xa + kk + lk4);
        float4 w4 = *(const float4*)(wa + kk + lk4);
        As[lk4 + 0][lrow] = a4.x; As[lk4 + 1][lrow] = a4.y;
        As[lk4 + 2][lrow] = a4.z; As[lk4 + 3][lrow] = a4.w;
        Ws[lk4 + 0][lrow] = w4.x; Ws[lk4 + 1][lrow] = w4.y;
        Ws[lk4 + 2][lrow] = w4.z; Ws[lk4 + 3][lrow] = w4.w;
        __syncthreads();

        #pragma unroll
        for (int k = 0; k < BKK; k++) {
            ulonglong2 a2 = *(const ulonglong2*)&As[k][ty * 4];
            float4 wf = *(const float4*)&Ws[k][tx * 4];
            unsigned long long w0 = pack2(wf.x, wf.x);
            unsigned long long w1 = pack2(wf.y, wf.y);
            unsigned long long w2 = pack2(wf.z, wf.z);
            unsigned long long w3 = pack2(wf.w, wf.w);
            fma2(acc2[0][0], a2.x, w0); fma2(acc2[0][1], a2.x, w1);
            fma2(acc2[0][2], a2.x, w2); fma2(acc2[0][3], a2.x, w3);
            fma2(acc2[1][0], a2.y, w0); fma2(acc2[1][1], a2.y, w1);
            fma2(acc2[1][2], a2.y, w2); fma2(acc2[1][3], a2.y, w3);
        }
        __syncthreads();
    }

    #pragma unroll
    for (int p = 0; p < 2; p++) {
        #pragma unroll
        for (int j = 0; j < 4; j++) {
            const int col = n0 + tx * 4 + j;
            const float bb = bias[col];
            dst[(size_t)(m0 + ty * 4 + 2 * p + 0) * DD + col] = lo32(acc2[p][j]) + bb;
            dst[(size_t)(m0 + ty * 4 + 2 * p + 1) * DD + col] = hi32(acc2[p][j]) + bb;
        }
    }
}

/* ================= persistent recurrence =================
 * 128 CTAs x 256 threads, all co-resident -> spin grid barrier safe.
 * CTA c owns d-slice [8c, 8c+8) for ALL b (lane = b, warp = k-eighth).
 * Both weight slices (8 rows of R_h + R_delta, 64 KB) live in smem,
 * loaded ONCE before the t-loop -> zero per-step weight traffic.
 * h is kept in a transposed double-buffered global array g_hT[par][k][b]
 * so the per-k h load is one coalesced 128B LDG per warp.
 */
#define SRSTRIDE 36                                  /* bank-spread pad   */
#define SMEM_W   (DD * 8 * 8)                        /* 65536 B packed w  */
#define SMEM_R   (16 * 8 * SRSTRIDE * 4)             /* 18432 B reduction */
#define SMEM_REC (SMEM_W + SMEM_R)

__device__ unsigned int g_bar = 0;
__device__ unsigned int g_gen = 0;

__device__ __forceinline__ void grid_sync() {
    __syncthreads();
    if (threadIdx.x == 0) {
        __threadfence();
        unsigned int gen = *((volatile unsigned int*)&g_gen);
        if (atomicAdd(&g_bar, 1) == 127u) {
            atomicExch(&g_bar, 0);
            __threadfence();
            atomicAdd(&g_gen, 1);
        } else {
            while (*((volatile unsigned int*)&g_gen) == gen) __nanosleep(32);
        }
        __threadfence();
    }
    __syncthreads();
}

__global__ __launch_bounds__(256, 1) void rec_kernel(
    const float* __restrict__ x,
    const float* __restrict__ h0,
    const float* __restrict__ Rh,
    const float* __restrict__ Rd,
    const float* __restrict__ bgate,
    float* __restrict__ outsec,
    float* __restrict__ hsec)
{
    extern __shared__ unsigned char smem[];
    unsigned long long* sWp = (unsigned long long*)smem;   /* [k][8] pairs  */
    float* sRed = (float*)(smem + SMEM_W);  /* [(w*2+m)*8+dl][SRSTRIDE]     */

    const int cta  = blockIdx.x;
    const int d0   = cta * 8;
    const int tid  = threadIdx.x;
    const int w    = tid >> 5;
    const int lane = tid & 31;

    /* ---- stage packed weight pairs into smem (once) ---- */
    #pragma unroll
    for (int m = 0; m < 2; m++) {
        const float* W = m ? Rd : Rh;
        #pragma unroll
        for (int p = 0; p < 4; p++) {
            const float* r0 = W + (size_t)(d0 + 2 * p)     * DD;
            const float* r1 = W + (size_t)(d0 + 2 * p + 1) * DD;
            for (int k = tid; k < DD; k += 256)
                sWp[k * 8 + m * 4 + p] = pack2(r0[k], r1[k]);
        }
    }

    /* ---- init transposed h[0]: CTA c fills rows [8c, 8c+8) ---- */
    g_hT[0][8 * cta + w][lane] = h0[(size_t)lane * DD + 8 * cta + w];

    grid_sync();   /* hT[0] visible everywhere; smem weights ready locally */

    const int kb  = w * 128;
    const int edl = tid & 7;        /* epilogue d-local */
    const int eb  = tid >> 3;       /* epilogue b       */
    const float bgv = bgate[d0 + edl];

    for (int t = 0; t < TT; t++) {
        const int cur = t & 1, nxt = cur ^ 1;
        const float* hcol = &g_hT[cur][0][lane];

        unsigned long long av0 = 0, av1 = 0, av2 = 0, av3 = 0;
        unsigned long long ad0 = 0, ad1 = 0, ad2 = 0, ad3 = 0;

        /* software-pipelined k loop: prefetch 8 h values ahead (MLP=8) */
        float hbuf[8];
        #pragma unroll
        for (int i = 0; i < 8; i++) hbuf[i] = __ldg(hcol + (size_t)(kb + i) * 32);

        #pragma unroll
        for (int g = 0; g < 16; g++) {
            float hnx[8];
            if (g < 15) {
                #pragma unroll
                for (int i = 0; i < 8; i++)
                    hnx[i] = __ldg(hcol + (size_t)(kb + (g + 1) * 8 + i) * 32);
            }
            #pragma unroll
            for (int i = 0; i < 8; i++) {
                const int k = kb + g * 8 + i;
                unsigned long long h2 = pack2(hbuf[i], hbuf[i]);
                ulonglong2 wv0 = *(const ulonglong2*)&sWp[k * 8 + 0];
                ulonglong2 wv1 = *(const ulonglong2*)&sWp[k * 8 + 2];
                ulonglong2 wd0 = *(const ulonglong2*)&sWp[k * 8 + 4];
                ulonglong2 wd1 = *(const ulonglong2*)&sWp[k * 8 + 6];
                fma2(av0, wv0.x, h2); fma2(av1, wv0.y, h2);
                fma2(av2, wv1.x, h2); fma2(av3, wv1.y, h2);
                fma2(ad0, wd0.x, h2); fma2(ad1, wd0.y, h2);
                fma2(ad2, wd1.x, h2); fma2(ad3, wd1.y, h2);
            }
            if (g < 15) {
                #pragma unroll
                for (int i = 0; i < 8; i++) hbuf[i] = hnx[i];
            }
        }

        /* stage per-warp partials: sRed[(w*2+m)*8 + d][b] */
        {
            float* r0 = sRed + ((w * 2 + 0) * 8) * SRSTRIDE + lane;
            float* r1 = sRed + ((w * 2 + 1) * 8) * SRSTRIDE + lane;
            r0[0 * SRSTRIDE] = lo32(av0); r0[1 * SRSTRIDE] = hi32(av0);
            r0[2 * SRSTRIDE] = lo32(av1); r0[3 * SRSTRIDE] = hi32(av1);
            r0[4 * SRSTRIDE] = lo32(av2); r0[5 * SRSTRIDE] = hi32(av2);
            r0[6 * SRSTRIDE] = lo32(av3); r0[7 * SRSTRIDE] = hi32(av3);
            r1[0 * SRSTRIDE] = lo32(ad0); r1[1 * SRSTRIDE] = hi32(ad0);
            r1[2 * SRSTRIDE] = lo32(ad1); r1[3 * SRSTRIDE] = hi32(ad1);
            r1[4 * SRSTRIDE] = lo32(ad2); r1[5 * SRSTRIDE] = hi32(ad2);
            r1[6 * SRSTRIDE] = lo32(ad3); r1[7 * SRSTRIDE] = hi32(ad3);
        }
        __syncthreads();

        /* ---- elementwise epilogue: thread -> (b=eb, d=d0+edl) ---- */
        {
            float sumv = 0.f, sumd = 0.f;
            #pragma unroll
            for (int kw = 0; kw < 8; kw++) {
                sumv += sRed[((kw * 2 + 0) * 8 + edl) * SRSTRIDE + eb];
                sumd += sRed[((kw * 2 + 1) * 8 + edl) * SRSTRIDE + eb];
            }
            const size_t idx = (size_t)t * BD + (size_t)eb * DD + d0 + edl;

            const float v     = outsec[idx]    + sumv;   /* stash xRx + h@Rh^T */
            const float dpre  = hsec[idx + BD] + sumd;   /* stash xWd + h@Rd^T */
            const float delta = 1.f / (1.f + expf(-dpre));
            const float hp    = hsec[idx];
            const float hn    = (1.f - delta) * hp + delta * tanhf(v);
            const float z     = hn + x[idx] + bgv;
            const float sig   = 1.f / (1.f + expf(-z));

            outsec[idx]          = hn * z * sig;   /* out[t]            */
            hsec[idx + BD]       = hn;             /* h[t+1] (output)   */
            g_hT[nxt][d0 + edl][eb] = hn;          /* h[t+1] transposed */
        }

        grid_sync();   /* publish h[t+1]; also guards sRed reuse */
    }
}

extern "C" void kernel_launch(void* const* d_in, const int* in_sizes, int n_in,
                              void* d_out, int out_size)
{
    const float* x   = (const float*)d_in[0];
    const float* h0  = (const float*)d_in[1];
    const float* Rh  = (const float*)d_in[2];
    const float* Rx  = (const float*)d_in[3];
    const float* Rd  = (const float*)d_in[4];
    const float* Wdl = (const float*)d_in[5];
    const float* b   = (const float*)d_in[6];
    const float* bd  = (const float*)d_in[7];
    const float* bgt = (const float*)d_in[8];

    float* outsec = (float*)d_out;          /* [T,B,D] outputs         */
    float* hsec   = outsec + (size_t)TBD;   /* [T+1,B,D] hidden states */

    cudaFuncSetAttribute(rec_kernel,
                         cudaFuncAttributeMaxDynamicSharedMemorySize,
                         (int)SMEM_REC);

    /* h[0] = h0 */
    cudaMemcpyAsync(hsec, h0, (size_t)BD * sizeof(float),
                    cudaMemcpyDeviceToDevice, 0);

    /* big input GEMM: stash xRx into out[t], xWd into h[t+1] */
    dim3 pgrid(TT * BB / BM, 2 * DD / BN);  /* (512, 32) */
    pre_gemm_kernel<<<pgrid, 256>>>(x, Rx, Wdl, b, bd, outsec, hsec);

    /* single persistent kernel for the whole scan */
    rec_kernel<<<128, 256, SMEM_REC>>>(x, h0, Rh, Rd, bgt, outsec, hsec);
}